// round 15
// baseline (speedup 1.0000x reference)
#include <cuda_runtime.h>
#include <cuda_fp16.h>

#define NPTS 1600
#define HPAD 1664           // 13*128 padded rows per head
#define CIN  256
#define ODIM 256
#define HD   64
#define NH   4
#define NKT  25
#define SCALE_L2E 0.090168439f   // log2(e)/16

#define SKB   144                 // attn smem row stride bytes
#define TILEB (64*SKB)            // 9216 per tile
#define SMEM_ATTN (4*TILEB)       // 36864

#define PAB   144                 // proj smem row stride bytes (B tile)
#define PBUF  (64*PAB)            // 9216 per B buffer
#define ONES_H2 0x3C003C00u

__device__ __align__(16) __half g_WhT[3*ODIM*CIN];     // [z][o][c] fp16 W^T
__device__ __align__(16) __half g_Qh[NH*HPAD*HD];
__device__ __align__(16) __half g_Kh[NH*HPAD*HD];
__device__ __align__(16) float  g_V  [NH*HPAD*HD];
__device__ __align__(16) unsigned g_Vt[NH*NKT*64*32];  // [h][kt][d][jp] half2
__device__ __align__(16) unsigned g_part[32*NPTS*32];  // half2 unnormalized O
__device__ float g_l[32*NPTS];

#define MMAH(c, a0, a1, a2, a3, b0, b1) \
    asm volatile("mma.sync.aligned.m16n8k16.row.col.f32.f16.f16.f32 " \
                 "{%0,%1,%2,%3},{%4,%5,%6,%7},{%8,%9},{%0,%1,%2,%3};" \
                 : "+f"((c)[0]), "+f"((c)[1]), "+f"((c)[2]), "+f"((c)[3]) \
                 : "r"(a0), "r"(a1), "r"(a2), "r"(a3), "r"(b0), "r"(b1))

#define LDSM4(r0, r1, r2, r3, a) \
    asm volatile("ldmatrix.sync.aligned.m8n8.x4.shared.b16 {%0,%1,%2,%3}, [%4];" \
                 : "=r"(r0), "=r"(r1), "=r"(r2), "=r"(r3) : "r"(a))

#define PACKH2(d, lo, hi) asm("cvt.rn.f16x2.f32 %0, %1, %2;" : "=r"(d) : "f"(hi), "f"(lo))
#define EX2H2(d) asm("ex2.approx.f16x2 %0, %0;" : "+r"(d))
#define CPA16(dst, src) \
    asm volatile("cp.async.cg.shared.global [%0], [%1], 16;" :: "r"(dst), "l"(src))
#define CPA_COMMIT() asm volatile("cp.async.commit_group;")
#define CPA_WAIT1()  asm volatile("cp.async.wait_group 1;")
#define CPA_WAIT0()  asm volatile("cp.async.wait_group 0;")

__device__ __forceinline__ unsigned smem_u32(const void* p) {
    unsigned a;
    asm("{ .reg .u64 t; cvta.to.shared.u64 t, %1; cvt.u32.u64 %0, t; }"
        : "=r"(a) : "l"(p));
    return a;
}

// ---------------------------------------------------------------------------
// convert: W{q,k,v} -> fp16 transposed [o][c] only. grid 96, block 256.
// ---------------------------------------------------------------------------
__global__ __launch_bounds__(256) void convert_kernel(
    const float* __restrict__ Wq, const float* __restrict__ Wk,
    const float* __restrict__ Wv)
{
    int t = blockIdx.x * 256 + threadIdx.x;      // < 3*ODIM*32
    int o  = t & 255;
    int c8 = (t >> 8) & 31;
    int z  = t >> 13;
    const float* W = (z == 0) ? Wq : (z == 1) ? Wk : Wv;
    __half tmp[8];
    #pragma unroll
    for (int i = 0; i < 8; i++)
        tmp[i] = __float2half_rn(W[(c8*8 + i)*ODIM + o]);
    *(uint4*)&g_WhT[(z*ODIM + o)*CIN + c8*8] = *(uint4*)tmp;
}

// ---------------------------------------------------------------------------
// QKV projection via fp16 mma (fp32 acc). A loaded DIRECTLY from fp32 x into
// fragment registers (no x-convert pass, no A smem); B (W^T fp16) cp.async
// double-buffered. grid (13, 4, 3), block 256.
// ---------------------------------------------------------------------------
__global__ __launch_bounds__(256) void proj_kernel(
    const float* __restrict__ x,
    const float* __restrict__ bq, const float* __restrict__ bk,
    const float* __restrict__ bv)
{
    __shared__ __align__(16) char ps[2*PBUF];
    const unsigned sbase = smem_u32(ps);
    const int tid = threadIdx.x;
    const int wid = tid >> 5, lane = tid & 31;
    const int g = lane >> 2, tg = lane & 3;
    const int zb = blockIdx.z;
    const int qn0 = blockIdx.x * 128, o0 = blockIdx.y * 64;
    const float* bias = (zb == 0) ? bq : (zb == 1) ? bk : bv;

    const unsigned boff = (unsigned)(((lane & 7) + ((lane & 16) >> 1))*PAB
                           + ((lane & 8) ? 16 : 0));

    const int row0 = qn0 + wid*16 + g;
    const int row1 = row0 + 8;
    const bool v0 = row0 < NPTS, v1 = row1 < NPTS;
    const float* x0p = x + (long)row0*CIN;
    const float* x1p = x + (long)row1*CIN;

    auto stageB = [&](int kc4, int b) {
        unsigned dstB = sbase + b*PBUF;
        #pragma unroll
        for (int it = 0; it < 2; it++) {
            int i4 = tid + it*256;
            int row = i4 >> 3, cs = i4 & 7;
            CPA16(dstB + row*PAB + cs*16,
                  (unsigned long long)__cvta_generic_to_global(
                      &g_WhT[(zb*ODIM + o0 + row)*CIN + kc4*64 + cs*8]));
        }
    };

    float c[8][4] = {};

    stageB(0, 0);
    CPA_COMMIT();

    for (int kc4 = 0; kc4 < 4; kc4++) {
        const int b = kc4 & 1;
        if (kc4 + 1 < 4) {
            stageB(kc4 + 1, b ^ 1);
            CPA_COMMIT();
            CPA_WAIT1();
        } else {
            CPA_WAIT0();
        }
        __syncthreads();

        const unsigned bbase = sbase + b*PBUF + boff;

        #pragma unroll
        for (int k16 = 0; k16 < 4; k16++) {
            // A fragments straight from global fp32 x
            int c0 = kc4*64 + k16*16 + 2*tg;
            float2 fa0 = v0 ? *(const float2*)&x0p[c0]     : make_float2(0.f, 0.f);
            float2 fa1 = v1 ? *(const float2*)&x1p[c0]     : make_float2(0.f, 0.f);
            float2 fa2 = v0 ? *(const float2*)&x0p[c0 + 8] : make_float2(0.f, 0.f);
            float2 fa3 = v1 ? *(const float2*)&x1p[c0 + 8] : make_float2(0.f, 0.f);
            unsigned a0, a1, a2, a3;
            PACKH2(a0, fa0.x, fa0.y);
            PACKH2(a1, fa1.x, fa1.y);
            PACKH2(a2, fa2.x, fa2.y);
            PACKH2(a3, fa3.x, fa3.y);
            #pragma unroll
            for (int np = 0; np < 4; np++) {
                unsigned b0, b1, b2, b3;
                LDSM4(b0, b1, b2, b3, bbase + np*(16*PAB) + k16*32);
                MMAH(c[2*np],   a0, a1, a2, a3, b0, b1);
                MMAH(c[2*np+1], a0, a1, a2, a3, b2, b3);
            }
        }
        __syncthreads();
    }

    const int head = blockIdx.y;
    #pragma unroll
    for (int n = 0; n < 8; n++) {
        int col = n*8 + 2*tg;
        float b0f = bias[o0 + col], b1f = bias[o0 + col + 1];
        float x0 = c[n][0] + b0f, x1 = c[n][1] + b1f;
        float x2 = c[n][2] + b0f, x3 = c[n][3] + b1f;
        if (zb == 0) {
            __half2 h0 = __floats2half2_rn(x0*SCALE_L2E, x1*SCALE_L2E);
            __half2 h1 = __floats2half2_rn(x2*SCALE_L2E, x3*SCALE_L2E);
            if (v0) *(unsigned*)&g_Qh[(head*HPAD + row0)*HD + col] = *(unsigned*)&h0;
            if (v1) *(unsigned*)&g_Qh[(head*HPAD + row1)*HD + col] = *(unsigned*)&h1;
        } else if (zb == 1) {
            __half2 h0 = __floats2half2_rn(x0, x1);
            __half2 h1 = __floats2half2_rn(x2, x3);
            if (v0) *(unsigned*)&g_Kh[(head*HPAD + row0)*HD + col] = *(unsigned*)&h0;
            if (v1) *(unsigned*)&g_Kh[(head*HPAD + row1)*HD + col] = *(unsigned*)&h1;
        } else {
            if (v0) *(float2*)&g_V[(head*HPAD + row0)*HD + col] = make_float2(x0, x1);
            if (v1) *(float2*)&g_V[(head*HPAD + row1)*HD + col] = make_float2(x2, x3);
        }
    }
}

// ---------------------------------------------------------------------------
// Vtilde (smem-tiled): one CTA per (head, key-tile). grid 100, block 256.
// ---------------------------------------------------------------------------
#define VSTR 76
__global__ __launch_bounds__(256) void vtilde_kernel()
{
    __shared__ float sv[HD*VSTR];   // [d][row 0..71]
    const int tid = threadIdx.x;
    const int h  = blockIdx.x / NKT;
    const int kt = blockIdx.x % NKT;
    const int j0 = kt*64 - 4;

    for (int i = tid; i < 72*16; i += 256) {
        int r  = i >> 4;
        int c4 = (i & 15) * 4;
        int jj = j0 + r;
        if (jj < 0) jj += NPTS; else if (jj >= NPTS) jj -= NPTS;
        float4 v = *(const float4*)&g_V[(h*HPAD + jj)*HD + c4];
        sv[(c4+0)*VSTR + r] = v.x;
        sv[(c4+1)*VSTR + r] = v.y;
        sv[(c4+2)*VSTR + r] = v.z;
        sv[(c4+3)*VSTR + r] = v.w;
    }
    __syncthreads();

    const int jp = tid & 31;
    const int d0 = (tid >> 5) * 8;
    unsigned* dst = g_Vt + ((h*NKT + kt)*64 + d0)*32 + jp;
    #pragma unroll
    for (int dd = 0; dd < 8; dd++) {
        const float* col = &sv[(d0 + dd)*VSTR + 2*jp];
        float v0 = col[0] + col[2] + col[4] + col[6] + col[8];
        float v1 = col[1] + col[3] + col[5] + col[7] + col[9];
        __half2 hh = __floats2half2_rn(v0, v1);
        dst[dd*32] = *(unsigned*)&hh;
    }
}

// ---------------------------------------------------------------------------
// fp16 mma.sync flash attention (R13 best config): 4 warps x m32 row tiles,
// register P, ldmatrix, cp.async double-buffer, MMA-based l, split-K=2.
// grid (13, 16, 2), block 128, 3 CTAs/SM.
// ---------------------------------------------------------------------------
__global__ void __launch_bounds__(128, 3) attn_kernel()
{
    extern __shared__ char smem[];
    const unsigned sbase = smem_u32(smem);
    const int tid = threadIdx.x;
    const int wid = tid >> 5, lane = tid & 31;
    const int g = lane >> 2, tg = lane & 3;

    const int qt = blockIdx.x, pair = blockIdx.y, sp = blockIdx.z;
    const int hq = pair >> 2, kh = pair & 3;
    const int h  = ((hq - kh + 1) & 3) - 1;      // in {-1,0,1,2}
    const int vh = (hq + h + 4) & 3;
    const int qn0 = qt * 128, r0 = wid * 32;
    const int kt0 = sp ? 13 : 0, ktN = sp ? 25 : 13;
    const int pidx = pair*2 + sp;

    const unsigned lmb = (unsigned)(((lane & 7) + ((lane & 16) >> 1))*SKB
                                    + ((lane & 8) ? 16 : 0));

    // ---- Q fragments: 2 m16 row tiles per warp ----
    unsigned qa[2][4][4];
    {
        const unsigned* Qg = (const unsigned*)g_Qh + (hq*HPAD + qn0 + r0)*32;
        #pragma unroll
        for (int t = 0; t < 2; t++)
            #pragma unroll
            for (int kc = 0; kc < 4; kc++) {
                qa[t][kc][0] = Qg[(t*16 + g    )*32 + kc*8 + tg    ];
                qa[t][kc][1] = Qg[(t*16 + g + 8)*32 + kc*8 + tg    ];
                qa[t][kc][2] = Qg[(t*16 + g    )*32 + kc*8 + tg + 4];
                qa[t][kc][3] = Qg[(t*16 + g + 8)*32 + kc*8 + tg + 4];
            }
    }

    const uint4* Kg = (const uint4*)g_Kh + (long)kh*HPAD*8;
    const uint4* Vg = (const uint4*)g_Vt + (long)vh*NKT*64*8;

    auto stage = [&](int kt, int b) {
        const uint4* Kt = Kg + kt*64*8;
        const uint4* Vt = Vg + kt*64*8;
        unsigned kd = sbase + b*TILEB;
        unsigned vd = sbase + (2 + b)*TILEB;
        #pragma unroll
        for (int it = 0; it < 4; it++) {
            int i4 = tid + it*128;
            unsigned off = (unsigned)((i4 >> 3)*SKB + (i4 & 7)*16);
            CPA16(kd + off, (unsigned long long)__cvta_generic_to_global(Kt + i4));
            CPA16(vd + off, (unsigned long long)__cvta_generic_to_global(Vt + i4));
        }
    };

    float o[2][8][4] = {};
    float lacc[2][4] = {};

    stage(kt0, 0);
    CPA_COMMIT();

    for (int kt = kt0; kt < ktN; kt++) {
        const int c = (kt - kt0) & 1;
        if (kt + 1 < ktN) {
            stage(kt + 1, c ^ 1);
            CPA_COMMIT();
            CPA_WAIT1();
        } else {
            CPA_WAIT0();
        }
        __syncthreads();

        const unsigned kadr = sbase + c*TILEB + lmb;
        const unsigned vadr = sbase + (2 + c)*TILEB + lmb;

        #pragma unroll
        for (int np = 0; np < 4; np++) {
            float s[2][2][4] = {};
            #pragma unroll
            for (int kc = 0; kc < 4; kc++) {
                unsigned b0, b1, b2, b3;
                LDSM4(b0, b1, b2, b3, kadr + np*(16*SKB) + kc*32);
                #pragma unroll
                for (int t = 0; t < 2; t++) {
                    MMAH(s[t][0], qa[t][kc][0], qa[t][kc][1], qa[t][kc][2], qa[t][kc][3], b0, b1);
                    MMAH(s[t][1], qa[t][kc][0], qa[t][kc][1], qa[t][kc][2], qa[t][kc][3], b2, b3);
                }
            }

            unsigned pa[2][4];
            #pragma unroll
            for (int t = 0; t < 2; t++) {
                PACKH2(pa[t][0], s[t][0][0], s[t][0][1]);  EX2H2(pa[t][0]);
                PACKH2(pa[t][1], s[t][0][2], s[t][0][3]);  EX2H2(pa[t][1]);
                PACKH2(pa[t][2], s[t][1][0], s[t][1][1]);  EX2H2(pa[t][2]);
                PACKH2(pa[t][3], s[t][1][2], s[t][1][3]);  EX2H2(pa[t][3]);
            }

            #pragma unroll
            for (int nn = 0; nn < 4; nn++) {
                unsigned b0, b1, b2, b3;
                LDSM4(b0, b1, b2, b3, vadr + nn*(16*SKB) + np*32);
                #pragma unroll
                for (int t = 0; t < 2; t++) {
                    MMAH(o[t][2*nn],   pa[t][0], pa[t][1], pa[t][2], pa[t][3], b0, b1);
                    MMAH(o[t][2*nn+1], pa[t][0], pa[t][1], pa[t][2], pa[t][3], b2, b3);
                }
            }
            #pragma unroll
            for (int t = 0; t < 2; t++)
                MMAH(lacc[t], pa[t][0], pa[t][1], pa[t][2], pa[t][3], ONES_H2, ONES_H2);
        }
        __syncthreads();
    }

    // ---- epilogue: write unnormalized O (fp16) + l for both row tiles ----
    unsigned* op = g_part + (long)pidx * NPTS * 32;
    #pragma unroll
    for (int t = 0; t < 2; t++) {
        const int row0 = qn0 + r0 + t*16 + g;
        const int row1 = row0 + 8;
        if (row0 < NPTS) {
            #pragma unroll
            for (int n = 0; n < 8; n++) {
                unsigned u; PACKH2(u, o[t][n][0], o[t][n][1]);
                op[row0*32 + n*4 + tg] = u;
            }
            if (tg == 0) g_l[pidx*NPTS + row0] = lacc[t][0];
        }
        if (row1 < NPTS) {
            #pragma unroll
            for (int n = 0; n < 8; n++) {
                unsigned u; PACKH2(u, o[t][n][2], o[t][n][3]);
                op[row1*32 + n*4 + tg] = u;
            }
            if (tg == 0) g_l[pidx*NPTS + row1] = lacc[t][2];
        }
    }
}

// ---------------------------------------------------------------------------
// out[n][a*64+d] = sum_kh wgt * (O_s0 + O_s1) / (l_s0 + l_s1)
// 8 outputs/thread, uint4 partial loads. grid 200, block 256.
// ---------------------------------------------------------------------------
__global__ __launch_bounds__(256) void combine_kernel(float* __restrict__ out)
{
    int idx8 = blockIdx.x * blockDim.x + threadIdx.x;
    int e  = idx8 * 8;
    int n  = e >> 8;
    int o  = e & 255;
    int a  = o >> 6, dd = o & 63;
    float acc[8] = {};
    #pragma unroll
    for (int khh = 0; khh < 4; khh++) {
        int hh = ((a - khh + 1) & 3) - 1;
        float wgt = (hh == 2) ? 2.0f : 1.0f;
        int p0 = (a*4 + khh)*2;
        float l = g_l[p0*NPTS + n] + g_l[(p0+1)*NPTS + n];
        float w = wgt / l;
        #pragma unroll
        for (int spp = 0; spp < 2; spp++) {
            uint4 u = *(const uint4*)(g_part + ((long)(p0+spp)*NPTS + n)*32 + (dd >> 1));
            float2 f0 = __half22float2(*(__half2*)&u.x);
            float2 f1 = __half22float2(*(__half2*)&u.y);
            float2 f2 = __half22float2(*(__half2*)&u.z);
            float2 f3 = __half22float2(*(__half2*)&u.w);
            acc[0] += w*f0.x; acc[1] += w*f0.y;
            acc[2] += w*f1.x; acc[3] += w*f1.y;
            acc[4] += w*f2.x; acc[5] += w*f2.y;
            acc[6] += w*f3.x; acc[7] += w*f3.y;
        }
    }
    *(float4*)&out[e]     = make_float4(acc[0], acc[1], acc[2], acc[3]);
    *(float4*)&out[e + 4] = make_float4(acc[4], acc[5], acc[6], acc[7]);
}

// ---------------------------------------------------------------------------
extern "C" void kernel_launch(void* const* d_in, const int* in_sizes, int n_in,
                              void* d_out, int out_size)
{
    const float* x  = (const float*)d_in[0];
    const float* Wq = (const float*)d_in[1];
    const float* bq = (const float*)d_in[2];
    const float* Wk = (const float*)d_in[3];
    const float* bk = (const float*)d_in[4];
    const float* Wv = (const float*)d_in[5];
    const float* bv = (const float*)d_in[6];
    float* out = (float*)d_out;

    cudaFuncSetAttribute(attn_kernel,
                         cudaFuncAttributeMaxDynamicSharedMemorySize, SMEM_ATTN);

    convert_kernel<<<3*ODIM*32/256, 256>>>(Wq, Wk, Wv);
    proj_kernel<<<dim3(13, 4, 3), 256>>>(x, bq, bk, bv);
    vtilde_kernel<<<NH*NKT, 256>>>();
    attn_kernel<<<dim3(13, 16, 2), 128, SMEM_ATTN>>>();
    combine_kernel<<<NPTS*ODIM/8/256, 256>>>(out);
}

// round 16
// speedup vs baseline: 1.0795x; 1.0795x over previous
#include <cuda_runtime.h>
#include <cuda_fp16.h>

#define NPTS 1600
#define HPAD 1664           // 13*128 padded rows per head
#define CIN  256
#define ODIM 256
#define HD   64
#define NH   4
#define NKT  25
#define SCALE_L2E 0.090168439f   // log2(e)/16

#define SKB   144                 // attn smem row stride bytes
#define TILEB (64*SKB)            // 9216 per tile
#define SMEM_ATTN (4*TILEB)       // 36864

#define PAB   144                 // proj smem row stride bytes
#define PA_OFF 0
#define PB_OFF (128*PAB)
#define ONES_H2 0x3C003C00u

__device__ __align__(16) __half g_xh [HPAD*CIN];
__device__ __align__(16) __half g_WhT[3*ODIM*CIN];
__device__ __align__(16) __half g_Qh[NH*HPAD*HD];
__device__ __align__(16) __half g_Kh[NH*HPAD*HD];
__device__ __align__(16) float  g_V  [NH*HPAD*HD];
__device__ __align__(16) unsigned g_Vt[NH*NKT*64*32];  // [h][kt][d][jp] half2
__device__ __align__(16) unsigned g_part[32*NPTS*32];  // half2 unnormalized O
__device__ float g_l[32*NPTS];

#define MMAH(c, a0, a1, a2, a3, b0, b1) \
    asm volatile("mma.sync.aligned.m16n8k16.row.col.f32.f16.f16.f32 " \
                 "{%0,%1,%2,%3},{%4,%5,%6,%7},{%8,%9},{%0,%1,%2,%3};" \
                 : "+f"((c)[0]), "+f"((c)[1]), "+f"((c)[2]), "+f"((c)[3]) \
                 : "r"(a0), "r"(a1), "r"(a2), "r"(a3), "r"(b0), "r"(b1))

#define LDSM4(r0, r1, r2, r3, a) \
    asm volatile("ldmatrix.sync.aligned.m8n8.x4.shared.b16 {%0,%1,%2,%3}, [%4];" \
                 : "=r"(r0), "=r"(r1), "=r"(r2), "=r"(r3) : "r"(a))

#define PACKH2(d, lo, hi) asm("cvt.rn.f16x2.f32 %0, %1, %2;" : "=r"(d) : "f"(hi), "f"(lo))
#define EX2H2(d) asm("ex2.approx.f16x2 %0, %0;" : "+r"(d))
#define CPA16(dst, src) \
    asm volatile("cp.async.cg.shared.global [%0], [%1], 16;" :: "r"(dst), "l"(src))
#define CPA_COMMIT() asm volatile("cp.async.commit_group;")
#define CPA_WAIT1()  asm volatile("cp.async.wait_group 1;")
#define CPA_WAIT0()  asm volatile("cp.async.wait_group 0;")

__device__ __forceinline__ unsigned smem_u32(const void* p) {
    unsigned a;
    asm("{ .reg .u64 t; cvta.to.shared.u64 t, %1; cvt.u32.u64 %0, t; }"
        : "=r"(a) : "l"(p));
    return a;
}

// ---------------------------------------------------------------------------
// convert: x -> fp16 (row layout), W{q,k,v} -> fp16 transposed [o][c]
// ---------------------------------------------------------------------------
__global__ __launch_bounds__(256) void convert_kernel(
    const float* __restrict__ x,
    const float* __restrict__ Wq, const float* __restrict__ Wk,
    const float* __restrict__ Wv)
{
    int id = blockIdx.x * 256 + threadIdx.x;
    if (id < NPTS*CIN/8) {
        int base = id * 8;
        float4 v0 = *(const float4*)&x[base];
        float4 v1 = *(const float4*)&x[base + 4];
        __half2 h0 = __floats2half2_rn(v0.x, v0.y);
        __half2 h1 = __floats2half2_rn(v0.z, v0.w);
        __half2 h2 = __floats2half2_rn(v1.x, v1.y);
        __half2 h3 = __floats2half2_rn(v1.z, v1.w);
        uint4 u = make_uint4(*(unsigned*)&h0, *(unsigned*)&h1,
                             *(unsigned*)&h2, *(unsigned*)&h3);
        *(uint4*)&g_xh[base] = u;
    } else if (id < NPTS*CIN/8 + 3*ODIM*32) {
        int t  = id - NPTS*CIN/8;
        int o  = t & 255;
        int c8 = (t >> 8) & 31;
        int z  = t >> 13;
        const float* W = (z == 0) ? Wq : (z == 1) ? Wk : Wv;
        __half tmp[8];
        #pragma unroll
        for (int i = 0; i < 8; i++)
            tmp[i] = __float2half_rn(W[(c8*8 + i)*ODIM + o]);
        *(uint4*)&g_WhT[(z*ODIM + o)*CIN + c8*8] = *(uint4*)tmp;
    }
}

// ---------------------------------------------------------------------------
// QKV projection via fp16 mma. grid (13, 4, 3), block 256 (8 warps).
// ---------------------------------------------------------------------------
__global__ __launch_bounds__(256) void proj_kernel(
    const float* __restrict__ bq, const float* __restrict__ bk,
    const float* __restrict__ bv)
{
    __shared__ __align__(16) char ps[PB_OFF + 64*PAB];
    const unsigned sbase = smem_u32(ps);
    const int tid = threadIdx.x;
    const int wid = tid >> 5, lane = tid & 31;
    const int g = lane >> 2, tg = lane & 3;
    const int zb = blockIdx.z;
    const int qn0 = blockIdx.x * 128, o0 = blockIdx.y * 64;
    const float* bias = (zb == 0) ? bq : (zb == 1) ? bk : bv;

    const unsigned abase = sbase + PA_OFF + (wid*16 + (lane & 15))*PAB
                           + ((lane & 16) ? 16 : 0);
    const unsigned bbase = sbase + PB_OFF + ((lane & 7) + ((lane & 16) >> 1))*PAB
                           + ((lane & 8) ? 16 : 0);

    float c[8][4] = {};

    for (int kc4 = 0; kc4 < 4; kc4++) {
        __syncthreads();
        #pragma unroll
        for (int it = 0; it < 4; it++) {
            int i4 = tid + it*256;
            int row = i4 >> 3, cs = i4 & 7;
            *(uint4*)(ps + PA_OFF + row*PAB + cs*16) =
                *(const uint4*)&g_xh[(qn0 + row)*CIN + kc4*64 + cs*8];
        }
        #pragma unroll
        for (int it = 0; it < 2; it++) {
            int i4 = tid + it*256;
            int row = i4 >> 3, cs = i4 & 7;
            *(uint4*)(ps + PB_OFF + row*PAB + cs*16) =
                *(const uint4*)&g_WhT[(zb*ODIM + o0 + row)*CIN + kc4*64 + cs*8];
        }
        __syncthreads();

        #pragma unroll
        for (int k16 = 0; k16 < 4; k16++) {
            unsigned a0, a1, a2, a3;
            LDSM4(a0, a1, a2, a3, abase + k16*32);
            #pragma unroll
            for (int np = 0; np < 4; np++) {
                unsigned b0, b1, b2, b3;
                LDSM4(b0, b1, b2, b3, bbase + np*(16*PAB) + k16*32);
                MMAH(c[2*np],   a0, a1, a2, a3, b0, b1);
                MMAH(c[2*np+1], a0, a1, a2, a3, b2, b3);
            }
        }
    }

    const int row0 = qn0 + wid*16 + g;
    const int row1 = row0 + 8;
    const int head = blockIdx.y;
    #pragma unroll
    for (int n = 0; n < 8; n++) {
        int col = n*8 + 2*tg;
        float b0f = bias[o0 + col], b1f = bias[o0 + col + 1];
        float x0 = c[n][0] + b0f, x1 = c[n][1] + b1f;
        float x2 = c[n][2] + b0f, x3 = c[n][3] + b1f;
        if (zb == 0) {
            __half2 h0 = __floats2half2_rn(x0*SCALE_L2E, x1*SCALE_L2E);
            __half2 h1 = __floats2half2_rn(x2*SCALE_L2E, x3*SCALE_L2E);
            if (row0 < NPTS) *(unsigned*)&g_Qh[(head*HPAD + row0)*HD + col] = *(unsigned*)&h0;
            if (row1 < NPTS) *(unsigned*)&g_Qh[(head*HPAD + row1)*HD + col] = *(unsigned*)&h1;
        } else if (zb == 1) {
            __half2 h0 = __floats2half2_rn(x0, x1);
            __half2 h1 = __floats2half2_rn(x2, x3);
            if (row0 < NPTS) *(unsigned*)&g_Kh[(head*HPAD + row0)*HD + col] = *(unsigned*)&h0;
            if (row1 < NPTS) *(unsigned*)&g_Kh[(head*HPAD + row1)*HD + col] = *(unsigned*)&h1;
        } else {
            if (row0 < NPTS) *(float2*)&g_V[(head*HPAD + row0)*HD + col] = make_float2(x0, x1);
            if (row1 < NPTS) *(float2*)&g_V[(head*HPAD + row1)*HD + col] = make_float2(x2, x3);
        }
    }
}

// ---------------------------------------------------------------------------
// Vtilde: 5-shift circular sums of V, fp16, stored transposed per key-tile.
// ---------------------------------------------------------------------------
__global__ __launch_bounds__(256) void vtilde_kernel()
{
    int idx = blockIdx.x * 256 + threadIdx.x;
    if (idx >= NH*NKT*32*16) return;
    int d4  = idx & 15;
    int jp  = (idx >> 4) & 31;
    int kt  = (idx >> 9) % NKT;
    int h   = idx / (NKT*512);

    int j0 = kt*64 + 2*jp;
    float4 a0 = make_float4(0.f,0.f,0.f,0.f);
    float4 a1 = make_float4(0.f,0.f,0.f,0.f);
    #pragma unroll
    for (int s = -4; s <= 4; s += 2) {
        int jj0 = j0 + s;     if (jj0 < 0) jj0 += NPTS; else if (jj0 >= NPTS) jj0 -= NPTS;
        int jj1 = j0 + 1 + s; if (jj1 < 0) jj1 += NPTS; else if (jj1 >= NPTS) jj1 -= NPTS;
        float4 v0 = *(const float4*)&g_V[(h*HPAD + jj0)*HD + d4*4];
        float4 v1 = *(const float4*)&g_V[(h*HPAD + jj1)*HD + d4*4];
        a0.x += v0.x; a0.y += v0.y; a0.z += v0.z; a0.w += v0.w;
        a1.x += v1.x; a1.y += v1.y; a1.z += v1.z; a1.w += v1.w;
    }
    float v0a[4] = {a0.x, a0.y, a0.z, a0.w};
    float v1a[4] = {a1.x, a1.y, a1.z, a1.w};
    #pragma unroll
    for (int i = 0; i < 4; i++) {
        __half2 hh = __floats2half2_rn(v0a[i], v1a[i]);
        g_Vt[(((h*NKT + kt)*64) + d4*4 + i)*32 + jp] = *(unsigned*)&hh;
    }
}

// ---------------------------------------------------------------------------
// fp16 mma.sync flash attention; 4 warps x m32 row tiles (B-frags shared by
// 2 row tiles), register P, ldmatrix, cp.async double-buffer, MMA-based l,
// split-K=2. grid (13, 16, 2), block 128, 3 CTAs/SM.
// ---------------------------------------------------------------------------
__global__ void __launch_bounds__(128, 3) attn_kernel()
{
    extern __shared__ char smem[];
    const unsigned sbase = smem_u32(smem);
    const int tid = threadIdx.x;
    const int wid = tid >> 5, lane = tid & 31;
    const int g = lane >> 2, tg = lane & 3;

    const int qt = blockIdx.x, pair = blockIdx.y, sp = blockIdx.z;
    const int hq = pair >> 2, kh = pair & 3;
    const int h  = ((hq - kh + 1) & 3) - 1;      // in {-1,0,1,2}
    const int vh = (hq + h + 4) & 3;
    const int qn0 = qt * 128, r0 = wid * 32;     // warp owns 32 rows
    const int kt0 = sp ? 13 : 0, ktN = sp ? 25 : 13;
    const int pidx = pair*2 + sp;

    const unsigned lmb = (unsigned)(((lane & 7) + ((lane & 16) >> 1))*SKB
                                    + ((lane & 8) ? 16 : 0));

    // ---- Q fragments: 2 m16 row tiles per warp ----
    unsigned qa[2][4][4];
    {
        const unsigned* Qg = (const unsigned*)g_Qh + (hq*HPAD + qn0 + r0)*32;
        #pragma unroll
        for (int t = 0; t < 2; t++)
            #pragma unroll
            for (int kc = 0; kc < 4; kc++) {
                qa[t][kc][0] = Qg[(t*16 + g    )*32 + kc*8 + tg    ];
                qa[t][kc][1] = Qg[(t*16 + g + 8)*32 + kc*8 + tg    ];
                qa[t][kc][2] = Qg[(t*16 + g    )*32 + kc*8 + tg + 4];
                qa[t][kc][3] = Qg[(t*16 + g + 8)*32 + kc*8 + tg + 4];
            }
    }

    const uint4* Kg = (const uint4*)g_Kh + (long)kh*HPAD*8;
    const uint4* Vg = (const uint4*)g_Vt + (long)vh*NKT*64*8;

    auto stage = [&](int kt, int b) {
        const uint4* Kt = Kg + kt*64*8;
        const uint4* Vt = Vg + kt*64*8;
        unsigned kd = sbase + b*TILEB;
        unsigned vd = sbase + (2 + b)*TILEB;
        #pragma unroll
        for (int it = 0; it < 4; it++) {
            int i4 = tid + it*128;
            unsigned off = (unsigned)((i4 >> 3)*SKB + (i4 & 7)*16);
            CPA16(kd + off, (unsigned long long)__cvta_generic_to_global(Kt + i4));
            CPA16(vd + off, (unsigned long long)__cvta_generic_to_global(Vt + i4));
        }
    };

    float o[2][8][4] = {};
    float lacc[2][4] = {};

    stage(kt0, 0);
    CPA_COMMIT();

    for (int kt = kt0; kt < ktN; kt++) {
        const int c = (kt - kt0) & 1;
        if (kt + 1 < ktN) {
            stage(kt + 1, c ^ 1);
            CPA_COMMIT();
            CPA_WAIT1();
        } else {
            CPA_WAIT0();
        }
        __syncthreads();

        const unsigned kadr = sbase + c*TILEB + lmb;
        const unsigned vadr = sbase + (2 + c)*TILEB + lmb;

        // ---- per np: QK (16 MMAs, B shared by both row tiles) -> exp -> PV ----
        #pragma unroll
        for (int np = 0; np < 4; np++) {
            float s[2][2][4] = {};
            #pragma unroll
            for (int kc = 0; kc < 4; kc++) {
                unsigned b0, b1, b2, b3;
                LDSM4(b0, b1, b2, b3, kadr + np*(16*SKB) + kc*32);
                #pragma unroll
                for (int t = 0; t < 2; t++) {
                    MMAH(s[t][0], qa[t][kc][0], qa[t][kc][1], qa[t][kc][2], qa[t][kc][3], b0, b1);
                    MMAH(s[t][1], qa[t][kc][0], qa[t][kc][1], qa[t][kc][2], qa[t][kc][3], b2, b3);
                }
            }

            unsigned pa[2][4];
            #pragma unroll
            for (int t = 0; t < 2; t++) {
                PACKH2(pa[t][0], s[t][0][0], s[t][0][1]);  EX2H2(pa[t][0]);
                PACKH2(pa[t][1], s[t][0][2], s[t][0][3]);  EX2H2(pa[t][1]);
                PACKH2(pa[t][2], s[t][1][0], s[t][1][1]);  EX2H2(pa[t][2]);
                PACKH2(pa[t][3], s[t][1][2], s[t][1][3]);  EX2H2(pa[t][3]);
            }

            #pragma unroll
            for (int nn = 0; nn < 4; nn++) {
                unsigned b0, b1, b2, b3;
                LDSM4(b0, b1, b2, b3, vadr + nn*(16*SKB) + np*32);
                #pragma unroll
                for (int t = 0; t < 2; t++) {
                    MMAH(o[t][2*nn],   pa[t][0], pa[t][1], pa[t][2], pa[t][3], b0, b1);
                    MMAH(o[t][2*nn+1], pa[t][0], pa[t][1], pa[t][2], pa[t][3], b2, b3);
                }
            }
            #pragma unroll
            for (int t = 0; t < 2; t++)
                MMAH(lacc[t], pa[t][0], pa[t][1], pa[t][2], pa[t][3], ONES_H2, ONES_H2);
        }
        __syncthreads();
    }

    // ---- epilogue: write unnormalized O (fp16) + l for both row tiles ----
    unsigned* op = g_part + (long)pidx * NPTS * 32;
    #pragma unroll
    for (int t = 0; t < 2; t++) {
        const int row0 = qn0 + r0 + t*16 + g;
        const int row1 = row0 + 8;
        if (row0 < NPTS) {
            #pragma unroll
            for (int n = 0; n < 8; n++) {
                unsigned u; PACKH2(u, o[t][n][0], o[t][n][1]);
                op[row0*32 + n*4 + tg] = u;
            }
            if (tg == 0) g_l[pidx*NPTS + row0] = lacc[t][0];
        }
        if (row1 < NPTS) {
            #pragma unroll
            for (int n = 0; n < 8; n++) {
                unsigned u; PACKH2(u, o[t][n][2], o[t][n][3]);
                op[row1*32 + n*4 + tg] = u;
            }
            if (tg == 0) g_l[pidx*NPTS + row1] = lacc[t][2];
        }
    }
}

// ---------------------------------------------------------------------------
// out[n][a*64+d] = sum_kh wgt * (O_s0 + O_s1) / (l_s0 + l_s1)
// ---------------------------------------------------------------------------
__global__ __launch_bounds__(256) void combine_kernel(float* __restrict__ out)
{
    int idx4 = blockIdx.x * blockDim.x + threadIdx.x;
    int e  = idx4 * 4;
    int n  = e >> 8;
    int o  = e & 255;
    int a  = o >> 6, dd = o & 63;
    float4 acc = make_float4(0.f, 0.f, 0.f, 0.f);
    #pragma unroll
    for (int khh = 0; khh < 4; khh++) {
        int hh = ((a - khh + 1) & 3) - 1;
        float wgt = (hh == 2) ? 2.0f : 1.0f;
        int p0 = (a*4 + khh)*2;
        float l = g_l[p0*NPTS + n] + g_l[(p0+1)*NPTS + n];
        float w = wgt / l;
        const unsigned* pp = g_part + ((long)p0*NPTS + n)*32 + (dd >> 1);
        uint2 u1 = *(const uint2*)pp;
        uint2 u2 = *(const uint2*)(pp + (long)NPTS*32);
        float2 a0 = __half22float2(*(__half2*)&u1.x);
        float2 a1 = __half22float2(*(__half2*)&u1.y);
        float2 b0 = __half22float2(*(__half2*)&u2.x);
        float2 b1 = __half22float2(*(__half2*)&u2.y);
        acc.x += w*(a0.x + b0.x);
        acc.y += w*(a0.y + b0.y);
        acc.z += w*(a1.x + b1.x);
        acc.w += w*(a1.y + b1.y);
    }
    *(float4*)&out[e] = acc;
}

// ---------------------------------------------------------------------------
extern "C" void kernel_launch(void* const* d_in, const int* in_sizes, int n_in,
                              void* d_out, int out_size)
{
    const float* x  = (const float*)d_in[0];
    const float* Wq = (const float*)d_in[1];
    const float* bq = (const float*)d_in[2];
    const float* Wk = (const float*)d_in[3];
    const float* bk = (const float*)d_in[4];
    const float* Wv = (const float*)d_in[5];
    const float* bv = (const float*)d_in[6];
    float* out = (float*)d_out;

    cudaFuncSetAttribute(attn_kernel,
                         cudaFuncAttributeMaxDynamicSharedMemorySize, SMEM_ATTN);

    convert_kernel<<<(NPTS*CIN/8 + 3*ODIM*32 + 255)/256, 256>>>(x, Wq, Wk, Wv);
    proj_kernel<<<dim3(13, 4, 3), 256>>>(bq, bk, bv);
    vtilde_kernel<<<(NH*NKT*32*16 + 255)/256, 256>>>();
    attn_kernel<<<dim3(13, 16, 2), 128, SMEM_ATTN>>>();
    combine_kernel<<<(NPTS*ODIM/4 + 255)/256, 256>>>(out);
}